// round 1
// baseline (speedup 1.0000x reference)
#include <cuda_runtime.h>
#include <cuda_bf16.h>
#include <math.h>

// Problem constants (fixed by the reference)
#define N_NODES 50000
#define FDIM    256
#define NCLS    40

// Scratch (allowed: __device__ globals, no runtime allocation)
__device__ float g_bufA[(size_t)N_NODES * FDIM];   // y1 / y2
__device__ float g_bufB[(size_t)N_NODES * FDIM];   // h1 (conv1 out, self-loop-initialized)
__device__ float g_bufC[(size_t)N_NODES * FDIM];   // h2
__device__ float g_logits[(size_t)N_NODES * NCLS];
__device__ float g_agg[(size_t)N_NODES * NCLS];

// ---------------------------------------------------------------------------
// GEMM: Y = relu(A[M,256] @ W[256,256] + bias), dual-written to Y and H2
// (H2 gets the self-loop contribution "for free").
// Tiling: BM=128, BN=64, BK=16, 256 threads, thread tile 8x4.
// ---------------------------------------------------------------------------
__global__ __launch_bounds__(256) void gemm_bias_relu(
    const float* __restrict__ A, const float* __restrict__ W,
    const float* __restrict__ bias, float* __restrict__ Y,
    float* __restrict__ H2)
{
    __shared__ float As[16][128];
    __shared__ float Ws[16][64];

    const int tid = threadIdx.x;
    const int tx = tid & 15;        // 0..15 -> 4 output cols each
    const int ty = tid >> 4;        // 0..15 -> 8 output rows each
    const int rowBase = blockIdx.y * 128;
    const int colBase = blockIdx.x * 64;

    float acc[8][4];
#pragma unroll
    for (int i = 0; i < 8; i++)
#pragma unroll
        for (int j = 0; j < 4; j++) acc[i][j] = 0.0f;

    for (int k0 = 0; k0 < FDIM; k0 += 16) {
        // Load A tile: 128 rows x 16 cols = 512 float4, 2 per thread
#pragma unroll
        for (int i = 0; i < 2; i++) {
            int idx = tid + i * 256;
            int r   = idx >> 2;         // 0..127
            int c4  = (idx & 3) * 4;    // 0,4,8,12
            float4 v = make_float4(0.f, 0.f, 0.f, 0.f);
            int gr = rowBase + r;
            if (gr < N_NODES)
                v = *(const float4*)(A + (size_t)gr * FDIM + k0 + c4);
            As[c4 + 0][r] = v.x;
            As[c4 + 1][r] = v.y;
            As[c4 + 2][r] = v.z;
            As[c4 + 3][r] = v.w;
        }
        // Load W tile: 16 rows x 64 cols = 256 float4, 1 per thread
        {
            int r  = tid >> 4;          // 0..15
            int c4 = (tid & 15) * 4;    // 0..60
            float4 v = *(const float4*)(W + (size_t)(k0 + r) * FDIM + colBase + c4);
            *(float4*)&Ws[r][c4] = v;
        }
        __syncthreads();

#pragma unroll
        for (int k = 0; k < 16; k++) {
            float4 a0 = *(const float4*)&As[k][ty * 8];
            float4 a1 = *(const float4*)&As[k][ty * 8 + 4];
            float4 wv = *(const float4*)&Ws[k][tx * 4];
            float av[8] = {a0.x, a0.y, a0.z, a0.w, a1.x, a1.y, a1.z, a1.w};
            float wr[4] = {wv.x, wv.y, wv.z, wv.w};
#pragma unroll
            for (int i = 0; i < 8; i++)
#pragma unroll
                for (int j = 0; j < 4; j++)
                    acc[i][j] = fmaf(av[i], wr[j], acc[i][j]);
        }
        __syncthreads();
    }

    float b[4];
#pragma unroll
    for (int j = 0; j < 4; j++) b[j] = bias[colBase + tx * 4 + j];

#pragma unroll
    for (int i = 0; i < 8; i++) {
        int gr = rowBase + ty * 8 + i;
        if (gr < N_NODES) {
            float4 o;
            o.x = fmaxf(acc[i][0] + b[0], 0.f);
            o.y = fmaxf(acc[i][1] + b[1], 0.f);
            o.z = fmaxf(acc[i][2] + b[2], 0.f);
            o.w = fmaxf(acc[i][3] + b[3], 0.f);
            size_t off = (size_t)gr * FDIM + colBase + tx * 4;
            *(float4*)(Y + off)  = o;
            *(float4*)(H2 + off) = o;
        }
    }
}

// ---------------------------------------------------------------------------
// Edge aggregation: H[dst] += Y[src] for every edge. One warp per edge,
// 2x float4 per lane, vector reductions (red.global.add.v4.f32).
// Y (51 MB) fits L2, so gathers hit L2; atomics also resolve in L2.
// ---------------------------------------------------------------------------
__global__ __launch_bounds__(256) void edge_aggregate(
    const float* __restrict__ Y, float* __restrict__ H,
    const int* __restrict__ src, const int* __restrict__ dst, int E)
{
    int w    = (blockIdx.x * blockDim.x + threadIdx.x) >> 5;
    int lane = threadIdx.x & 31;
    if (w >= E) return;
    int s = __ldg(src + w);
    int d = __ldg(dst + w);
    const float4* ys = (const float4*)(Y + (size_t)s * FDIM);
    float4 v0 = __ldg(ys + lane);
    float4 v1 = __ldg(ys + lane + 32);
    float* hp = H + (size_t)d * FDIM;
    asm volatile("red.global.add.v4.f32 [%0], {%1,%2,%3,%4};"
                 :: "l"(hp + lane * 4), "f"(v0.x), "f"(v0.y), "f"(v0.z), "f"(v0.w)
                 : "memory");
    asm volatile("red.global.add.v4.f32 [%0], {%1,%2,%3,%4};"
                 :: "l"(hp + 128 + lane * 4), "f"(v1.x), "f"(v1.y), "f"(v1.z), "f"(v1.w)
                 : "memory");
}

// ---------------------------------------------------------------------------
// FC: logits[N,40] = H[N,256] @ Wfc[256,40] + bfc. Thread per (row, class).
// ---------------------------------------------------------------------------
__global__ __launch_bounds__(256) void fc_kernel(
    const float* __restrict__ Hf, const float* __restrict__ Wfc,
    const float* __restrict__ bfc, float* __restrict__ L)
{
    int c = threadIdx.x & 63;
    int r = blockIdx.x * 4 + (threadIdx.x >> 6);
    if (r >= N_NODES || c >= NCLS) return;
    const float* hr = Hf + (size_t)r * FDIM;
    float acc = __ldg(bfc + c);
#pragma unroll 4
    for (int k = 0; k < FDIM; k += 4) {
        float4 h4 = *(const float4*)(hr + k);
        acc = fmaf(h4.x, __ldg(Wfc + (k + 0) * NCLS + c), acc);
        acc = fmaf(h4.y, __ldg(Wfc + (k + 1) * NCLS + c), acc);
        acc = fmaf(h4.z, __ldg(Wfc + (k + 2) * NCLS + c), acc);
        acc = fmaf(h4.w, __ldg(Wfc + (k + 3) * NCLS + c), acc);
    }
    L[(size_t)r * NCLS + c] = acc;
}

__global__ __launch_bounds__(256) void zero_kernel(float* __restrict__ p, int n)
{
    int i = blockIdx.x * blockDim.x + threadIdx.x;
    if (i < n) p[i] = 0.0f;
}

// ---------------------------------------------------------------------------
// Sparse PvT: Agg[row] += val * logits[col]. One warp per nonzero,
// lanes cover the 40 classes (lane and 32+lane for lanes < 8).
// ---------------------------------------------------------------------------
__global__ __launch_bounds__(256) void pvt_kernel(
    const float* __restrict__ L, float* __restrict__ Agg,
    const int* __restrict__ row, const int* __restrict__ col,
    const float* __restrict__ val, int nnz)
{
    int w    = (blockIdx.x * blockDim.x + threadIdx.x) >> 5;
    int lane = threadIdx.x & 31;
    if (w >= nnz) return;
    int   r = __ldg(row + w);
    int   c = __ldg(col + w);
    float v = __ldg(val + w);
    const float* lr = L + (size_t)c * NCLS;
    float*       ar = Agg + (size_t)r * NCLS;
    atomicAdd(ar + lane, v * __ldg(lr + lane));
    if (lane < 8)
        atomicAdd(ar + 32 + lane, v * __ldg(lr + 32 + lane));
}

// ---------------------------------------------------------------------------
// Row-wise log-softmax over 40 classes. One warp per row.
// ---------------------------------------------------------------------------
__global__ __launch_bounds__(256) void logsoftmax_kernel(
    const float* __restrict__ Agg, float* __restrict__ out)
{
    int w    = (blockIdx.x * blockDim.x + threadIdx.x) >> 5;
    int lane = threadIdx.x & 31;
    if (w >= N_NODES) return;
    const float* a = Agg + (size_t)w * NCLS;
    float x0 = a[lane];
    float x1 = (lane < 8) ? a[32 + lane] : -INFINITY;
    float m = fmaxf(x0, x1);
#pragma unroll
    for (int off = 16; off > 0; off >>= 1)
        m = fmaxf(m, __shfl_xor_sync(0xffffffffu, m, off));
    float e = __expf(x0 - m) + ((lane < 8) ? __expf(x1 - m) : 0.0f);
#pragma unroll
    for (int off = 16; off > 0; off >>= 1)
        e += __shfl_xor_sync(0xffffffffu, e, off);
    float ls = logf(e);
    float* o = out + (size_t)w * NCLS;
    o[lane] = x0 - m - ls;
    if (lane < 8) o[32 + lane] = x1 - m - ls;
}

// ---------------------------------------------------------------------------
extern "C" void kernel_launch(void* const* d_in, const int* in_sizes, int n_in,
                              void* d_out, int out_size)
{
    const float* x    = (const float*)d_in[0];
    const int*   esrc = (const int*)  d_in[1];
    const int*   edst = (const int*)  d_in[2];
    const int*   prow = (const int*)  d_in[3];
    const int*   pcol = (const int*)  d_in[4];
    const float* pval = (const float*)d_in[5];
    const float* w1   = (const float*)d_in[6];
    const float* b1   = (const float*)d_in[7];
    const float* w2   = (const float*)d_in[8];
    const float* b2   = (const float*)d_in[9];
    const float* wfc  = (const float*)d_in[10];
    const float* bfc  = (const float*)d_in[11];
    const int E   = in_sizes[1];
    const int nnz = in_sizes[3];

    float *bufA, *bufB, *bufC, *logits, *agg;
    cudaGetSymbolAddress((void**)&bufA,   g_bufA);
    cudaGetSymbolAddress((void**)&bufB,   g_bufB);
    cudaGetSymbolAddress((void**)&bufC,   g_bufC);
    cudaGetSymbolAddress((void**)&logits, g_logits);
    cudaGetSymbolAddress((void**)&agg,    g_agg);

    dim3 gemm_grid(FDIM / 64, (N_NODES + 127) / 128);
    int  edge_blocks = (int)(((long long)E * 32 + 255) / 256);

    // conv1: y1 = relu(x @ w1 + b1); h1 = y1 (self loop) + scatter edges
    gemm_bias_relu<<<gemm_grid, 256>>>(x, w1, b1, bufA, bufB);
    edge_aggregate<<<edge_blocks, 256>>>(bufA, bufB, esrc, edst, E);

    // conv2: y2 = relu(h1 @ w2 + b2); h2 = y2 + scatter edges
    gemm_bias_relu<<<gemm_grid, 256>>>(bufB, w2, b2, bufA, bufC);
    edge_aggregate<<<edge_blocks, 256>>>(bufA, bufC, esrc, edst, E);

    // classifier head
    fc_kernel<<<(N_NODES + 3) / 4, 256>>>(bufC, wfc, bfc, logits);

    // PvT @ logits
    zero_kernel<<<(N_NODES * NCLS + 255) / 256, 256>>>(agg, N_NODES * NCLS);
    pvt_kernel<<<(int)(((long long)nnz * 32 + 255) / 256), 256>>>(
        logits, agg, prow, pcol, pval, nnz);

    // log-softmax -> output
    logsoftmax_kernel<<<(int)(((long long)N_NODES * 32 + 255) / 256), 256>>>(
        agg, (float*)d_out);
}

// round 2
// speedup vs baseline: 1.3495x; 1.3495x over previous
#include <cuda_runtime.h>
#include <cuda_bf16.h>
#include <math.h>

#define N_NODES 50000
#define FDIM    256
#define NCLS    40
#define MAX_E   1700000

// Scratch (device globals only — no runtime allocation)
__device__ float g_bufA[(size_t)N_NODES * FDIM];   // y (GEMM out)
__device__ float g_bufB[(size_t)N_NODES * FDIM];   // h1
__device__ float g_bufC[(size_t)N_NODES * FDIM];   // h2
__device__ float g_logits[(size_t)N_NODES * NCLS];
__device__ float g_agg[(size_t)N_NODES * NCLS];
__device__ int   g_sortedSrc[MAX_E];
__device__ int   g_rowStart[N_NODES + 1];
__device__ int   g_deg[N_NODES];
__device__ int   g_cursor[N_NODES];

// ---------------------------------------------------------------------------
// CSR build: histogram by dst, exclusive scan, stable-ish scatter of src ids.
// ---------------------------------------------------------------------------
__global__ __launch_bounds__(256) void zero2_i32(int* __restrict__ a,
                                                 int* __restrict__ b, int n)
{
    int i = blockIdx.x * blockDim.x + threadIdx.x;
    if (i < n) { a[i] = 0; b[i] = 0; }
}

__global__ __launch_bounds__(256) void hist_kernel(
    const int* __restrict__ dst, int* __restrict__ deg, int E)
{
    int i = blockIdx.x * blockDim.x + threadIdx.x;
    if (i < E) atomicAdd(&deg[__ldg(dst + i)], 1);
}

__global__ __launch_bounds__(1024) void scan_kernel(
    const int* __restrict__ deg, int* __restrict__ rowStart)
{
    __shared__ int sums[1024];
    const int tid = threadIdx.x;
    const int CH  = (N_NODES + 1023) / 1024;   // 49
    const int base = tid * CH;
    int s = 0;
    for (int i = 0; i < CH; i++) {
        int idx = base + i;
        if (idx < N_NODES) s += deg[idx];
    }
    sums[tid] = s;
    __syncthreads();
    for (int off = 1; off < 1024; off <<= 1) {
        int v = (tid >= off) ? sums[tid - off] : 0;
        __syncthreads();
        sums[tid] += v;
        __syncthreads();
    }
    int run = sums[tid] - s;   // exclusive prefix of this chunk
    for (int i = 0; i < CH; i++) {
        int idx = base + i;
        if (idx < N_NODES) { rowStart[idx] = run; run += deg[idx]; }
    }
    if (tid == 1023) rowStart[N_NODES] = run;
}

__global__ __launch_bounds__(256) void scatter_kernel(
    const int* __restrict__ src, const int* __restrict__ dst,
    const int* __restrict__ rowStart, int* __restrict__ cursor,
    int* __restrict__ sortedSrc, int E)
{
    int i = blockIdx.x * blockDim.x + threadIdx.x;
    if (i >= E) return;
    int d = __ldg(dst + i);
    int pos = __ldg(rowStart + d) + atomicAdd(&cursor[d], 1);
    sortedSrc[pos] = __ldg(src + i);
}

// ---------------------------------------------------------------------------
// GEMM: Y = relu(A[M,256] @ W[256,256] + bias).
// BM=128, BN=128, BK=8, 256 threads, 8x8 per-thread tile.
// ---------------------------------------------------------------------------
__global__ __launch_bounds__(256) void gemm_bias_relu(
    const float* __restrict__ A, const float* __restrict__ W,
    const float* __restrict__ bias, float* __restrict__ Y)
{
    __shared__ float As[8][128];
    __shared__ float Ws[8][128];

    const int tid = threadIdx.x;
    const int tx = tid & 15;        // col group (8 cols)
    const int ty = tid >> 4;        // row group (8 rows)
    const int rowBase = blockIdx.y * 128;
    const int colBase = blockIdx.x * 128;

    float acc[8][8];
#pragma unroll
    for (int i = 0; i < 8; i++)
#pragma unroll
        for (int j = 0; j < 8; j++) acc[i][j] = 0.0f;

    for (int k0 = 0; k0 < FDIM; k0 += 8) {
        // A tile: 128 rows x 8 cols = 256 float4, 1 per thread (transposed)
        {
            int r  = tid >> 1;          // 0..127
            int c4 = (tid & 1) * 4;     // 0 or 4
            float4 v = make_float4(0.f, 0.f, 0.f, 0.f);
            int gr = rowBase + r;
            if (gr < N_NODES)
                v = *(const float4*)(A + (size_t)gr * FDIM + k0 + c4);
            As[c4 + 0][r] = v.x;
            As[c4 + 1][r] = v.y;
            As[c4 + 2][r] = v.z;
            As[c4 + 3][r] = v.w;
        }
        // W tile: 8 rows x 128 cols = 256 float4, 1 per thread
        {
            int r  = tid >> 5;          // 0..7
            int c4 = (tid & 31) * 4;    // 0..124
            *(float4*)&Ws[r][c4] =
                *(const float4*)(W + (size_t)(k0 + r) * FDIM + colBase + c4);
        }
        __syncthreads();

#pragma unroll
        for (int k = 0; k < 8; k++) {
            float4 a0 = *(const float4*)&As[k][ty * 8];
            float4 a1 = *(const float4*)&As[k][ty * 8 + 4];
            float4 w0 = *(const float4*)&Ws[k][tx * 8];
            float4 w1 = *(const float4*)&Ws[k][tx * 8 + 4];
            float av[8] = {a0.x, a0.y, a0.z, a0.w, a1.x, a1.y, a1.z, a1.w};
            float wv[8] = {w0.x, w0.y, w0.z, w0.w, w1.x, w1.y, w1.z, w1.w};
#pragma unroll
            for (int i = 0; i < 8; i++)
#pragma unroll
                for (int j = 0; j < 8; j++)
                    acc[i][j] = fmaf(av[i], wv[j], acc[i][j]);
        }
        __syncthreads();
    }

    float b[8];
#pragma unroll
    for (int j = 0; j < 8; j++) b[j] = bias[colBase + tx * 8 + j];

#pragma unroll
    for (int i = 0; i < 8; i++) {
        int gr = rowBase + ty * 8 + i;
        if (gr < N_NODES) {
            size_t off = (size_t)gr * FDIM + colBase + tx * 8;
            float4 o0, o1;
            o0.x = fmaxf(acc[i][0] + b[0], 0.f);
            o0.y = fmaxf(acc[i][1] + b[1], 0.f);
            o0.z = fmaxf(acc[i][2] + b[2], 0.f);
            o0.w = fmaxf(acc[i][3] + b[3], 0.f);
            o1.x = fmaxf(acc[i][4] + b[4], 0.f);
            o1.y = fmaxf(acc[i][5] + b[5], 0.f);
            o1.z = fmaxf(acc[i][6] + b[6], 0.f);
            o1.w = fmaxf(acc[i][7] + b[7], 0.f);
            *(float4*)(Y + off)     = o0;
            *(float4*)(Y + off + 4) = o1;
        }
    }
}

// ---------------------------------------------------------------------------
// CSR gather aggregation: H[v] = Y[v] (self loop) + sum_{e in CSR(v)} Y[src].
// One warp per dst node; each lane carries 8 floats (2 float4) in registers.
// All reads hit L2 (Y = 51 MB < 126 MB L2); single streaming write, no atomics.
// ---------------------------------------------------------------------------
__device__ __forceinline__ void f4add(float4& a, const float4 b)
{
    a.x += b.x; a.y += b.y; a.z += b.z; a.w += b.w;
}

__global__ __launch_bounds__(256) void aggregate_csr(
    const float* __restrict__ Y, float* __restrict__ H,
    const int* __restrict__ rowStart, const int* __restrict__ ssrc)
{
    int node = blockIdx.x * 8 + (threadIdx.x >> 5);
    int lane = threadIdx.x & 31;
    if (node >= N_NODES) return;

    const float4* yb = (const float4*)Y;
    size_t selfOff = (size_t)node * 64;          // row in float4 units
    float4 a0 = __ldg(yb + selfOff + lane);
    float4 a1 = __ldg(yb + selfOff + lane + 32);

    int e    = __ldg(rowStart + node);
    int eEnd = __ldg(rowStart + node + 1);

    for (; e + 2 <= eEnd; e += 2) {
        int s0 = __ldg(ssrc + e);
        int s1 = __ldg(ssrc + e + 1);
        const float4* p0 = yb + (size_t)s0 * 64;
        const float4* p1 = yb + (size_t)s1 * 64;
        float4 u0 = __ldg(p0 + lane);
        float4 u1 = __ldg(p0 + lane + 32);
        float4 v0 = __ldg(p1 + lane);
        float4 v1 = __ldg(p1 + lane + 32);
        f4add(a0, u0); f4add(a1, u1);
        f4add(a0, v0); f4add(a1, v1);
    }
    if (e < eEnd) {
        int s0 = __ldg(ssrc + e);
        const float4* p0 = yb + (size_t)s0 * 64;
        f4add(a0, __ldg(p0 + lane));
        f4add(a1, __ldg(p0 + lane + 32));
    }

    float4* hb = (float4*)H + selfOff;
    hb[lane]      = a0;
    hb[lane + 32] = a1;
}

// ---------------------------------------------------------------------------
// FC: logits[N,40] = H[N,256] @ Wfc[256,40] + bfc.
// ---------------------------------------------------------------------------
__global__ __launch_bounds__(256) void fc_kernel(
    const float* __restrict__ Hf, const float* __restrict__ Wfc,
    const float* __restrict__ bfc, float* __restrict__ L)
{
    int c = threadIdx.x & 63;
    int r = blockIdx.x * 4 + (threadIdx.x >> 6);
    if (r >= N_NODES || c >= NCLS) return;
    const float* hr = Hf + (size_t)r * FDIM;
    float acc = __ldg(bfc + c);
#pragma unroll 4
    for (int k = 0; k < FDIM; k += 4) {
        float4 h4 = *(const float4*)(hr + k);
        acc = fmaf(h4.x, __ldg(Wfc + (k + 0) * NCLS + c), acc);
        acc = fmaf(h4.y, __ldg(Wfc + (k + 1) * NCLS + c), acc);
        acc = fmaf(h4.z, __ldg(Wfc + (k + 2) * NCLS + c), acc);
        acc = fmaf(h4.w, __ldg(Wfc + (k + 3) * NCLS + c), acc);
    }
    L[(size_t)r * NCLS + c] = acc;
}

__global__ __launch_bounds__(256) void zero_f32(float* __restrict__ p, int n)
{
    int i = blockIdx.x * blockDim.x + threadIdx.x;
    if (i < n) p[i] = 0.0f;
}

// ---------------------------------------------------------------------------
// Sparse PvT: Agg[row] += val * logits[col]. One warp per nonzero.
// ---------------------------------------------------------------------------
__global__ __launch_bounds__(256) void pvt_kernel(
    const float* __restrict__ L, float* __restrict__ Agg,
    const int* __restrict__ row, const int* __restrict__ col,
    const float* __restrict__ val, int nnz)
{
    int w    = (blockIdx.x * blockDim.x + threadIdx.x) >> 5;
    int lane = threadIdx.x & 31;
    if (w >= nnz) return;
    int   r = __ldg(row + w);
    int   c = __ldg(col + w);
    float v = __ldg(val + w);
    const float* lr = L + (size_t)c * NCLS;
    float*       ar = Agg + (size_t)r * NCLS;
    atomicAdd(ar + lane, v * __ldg(lr + lane));
    if (lane < 8)
        atomicAdd(ar + 32 + lane, v * __ldg(lr + 32 + lane));
}

// ---------------------------------------------------------------------------
// Row-wise log-softmax over 40 classes. One warp per row.
// ---------------------------------------------------------------------------
__global__ __launch_bounds__(256) void logsoftmax_kernel(
    const float* __restrict__ Agg, float* __restrict__ out)
{
    int w    = (blockIdx.x * blockDim.x + threadIdx.x) >> 5;
    int lane = threadIdx.x & 31;
    if (w >= N_NODES) return;
    const float* a = Agg + (size_t)w * NCLS;
    float x0 = a[lane];
    float x1 = (lane < 8) ? a[32 + lane] : -INFINITY;
    float m = fmaxf(x0, x1);
#pragma unroll
    for (int off = 16; off > 0; off >>= 1)
        m = fmaxf(m, __shfl_xor_sync(0xffffffffu, m, off));
    float e = __expf(x0 - m) + ((lane < 8) ? __expf(x1 - m) : 0.0f);
#pragma unroll
    for (int off = 16; off > 0; off >>= 1)
        e += __shfl_xor_sync(0xffffffffu, e, off);
    float ls = logf(e);
    float* o = out + (size_t)w * NCLS;
    o[lane] = x0 - m - ls;
    if (lane < 8) o[32 + lane] = x1 - m - ls;
}

// ---------------------------------------------------------------------------
extern "C" void kernel_launch(void* const* d_in, const int* in_sizes, int n_in,
                              void* d_out, int out_size)
{
    const float* x    = (const float*)d_in[0];
    const int*   esrc = (const int*)  d_in[1];
    const int*   edst = (const int*)  d_in[2];
    const int*   prow = (const int*)  d_in[3];
    const int*   pcol = (const int*)  d_in[4];
    const float* pval = (const float*)d_in[5];
    const float* w1   = (const float*)d_in[6];
    const float* b1   = (const float*)d_in[7];
    const float* w2   = (const float*)d_in[8];
    const float* b2   = (const float*)d_in[9];
    const float* wfc  = (const float*)d_in[10];
    const float* bfc  = (const float*)d_in[11];
    const int E   = in_sizes[1];
    const int nnz = in_sizes[3];

    float *bufA, *bufB, *bufC, *logits, *agg;
    int *ssrc, *rowStart, *deg, *cursor;
    cudaGetSymbolAddress((void**)&bufA,     g_bufA);
    cudaGetSymbolAddress((void**)&bufB,     g_bufB);
    cudaGetSymbolAddress((void**)&bufC,     g_bufC);
    cudaGetSymbolAddress((void**)&logits,   g_logits);
    cudaGetSymbolAddress((void**)&agg,      g_agg);
    cudaGetSymbolAddress((void**)&ssrc,     g_sortedSrc);
    cudaGetSymbolAddress((void**)&rowStart, g_rowStart);
    cudaGetSymbolAddress((void**)&deg,      g_deg);
    cudaGetSymbolAddress((void**)&cursor,   g_cursor);

    // --- CSR build (dst-sorted edge list), reused by both convs ---
    zero2_i32<<<(N_NODES + 255) / 256, 256>>>(deg, cursor, N_NODES);
    hist_kernel<<<(E + 255) / 256, 256>>>(edst, deg, E);
    scan_kernel<<<1, 1024>>>(deg, rowStart);
    scatter_kernel<<<(E + 255) / 256, 256>>>(esrc, edst, rowStart, cursor,
                                             ssrc, E);

    dim3 gemm_grid(FDIM / 128, (N_NODES + 127) / 128);
    int  agg_blocks = (N_NODES + 7) / 8;

    // conv1
    gemm_bias_relu<<<gemm_grid, 256>>>(x, w1, b1, bufA);
    aggregate_csr<<<agg_blocks, 256>>>(bufA, bufB, rowStart, ssrc);

    // conv2
    gemm_bias_relu<<<gemm_grid, 256>>>(bufB, w2, b2, bufA);
    aggregate_csr<<<agg_blocks, 256>>>(bufA, bufC, rowStart, ssrc);

    // classifier head
    fc_kernel<<<(N_NODES + 3) / 4, 256>>>(bufC, wfc, bfc, logits);

    zero_f32<<<(N_NODES * NCLS + 255) / 256, 256>>>(agg, N_NODES * NCLS);
    pvt_kernel<<<(int)(((long long)nnz * 32 + 255) / 256), 256>>>(
        logits, agg, prow, pcol, pval, nnz);

    logsoftmax_kernel<<<(int)(((long long)N_NODES * 32 + 255) / 256), 256>>>(
        agg, (float*)d_out);
}

// round 5
// speedup vs baseline: 1.5114x; 1.1199x over previous
#include <cuda_runtime.h>
#include <cuda_fp16.h>
#include <math.h>

#define N_NODES 50000
#define FDIM    256
#define NCLS    40
#define MAX_E   1700000

// Scratch (device globals only — no runtime allocation)
__device__ __half g_Yh[(size_t)N_NODES * FDIM];    // GEMM out (fp16, gather src)
__device__ float  g_h1[(size_t)N_NODES * FDIM];    // conv1 aggregate (fp32)
__device__ float  g_h2[(size_t)N_NODES * FDIM];    // conv2 aggregate (fp32)
__device__ float  g_logits[(size_t)N_NODES * NCLS];
__device__ float  g_agg[(size_t)N_NODES * NCLS];
__device__ int    g_sortedSrc[MAX_E];
__device__ int    g_rowStart[N_NODES + 1];
__device__ int    g_deg[N_NODES];
__device__ int    g_cursor[N_NODES];

// ---------------------------------------------------------------------------
// CSR build: histogram by dst, exclusive scan, scatter of src ids.
// ---------------------------------------------------------------------------
__global__ __launch_bounds__(256) void zero2_i32(int* __restrict__ a,
                                                 int* __restrict__ b, int n)
{
    int i = blockIdx.x * blockDim.x + threadIdx.x;
    if (i < n) { a[i] = 0; b[i] = 0; }
}

__global__ __launch_bounds__(256) void hist_kernel(
    const int* __restrict__ dst, int* __restrict__ deg, int E)
{
    int i = blockIdx.x * blockDim.x + threadIdx.x;
    if (i < E) atomicAdd(&deg[__ldg(dst + i)], 1);
}

__global__ __launch_bounds__(1024) void scan_kernel(
    const int* __restrict__ deg, int* __restrict__ rowStart)
{
    __shared__ int sums[1024];
    const int tid = threadIdx.x;
    const int CH  = (N_NODES + 1023) / 1024;   // 49
    const int base = tid * CH;
    int s = 0;
    for (int i = 0; i < CH; i++) {
        int idx = base + i;
        if (idx < N_NODES) s += deg[idx];
    }
    sums[tid] = s;
    __syncthreads();
    for (int off = 1; off < 1024; off <<= 1) {
        int v = (tid >= off) ? sums[tid - off] : 0;
        __syncthreads();
        sums[tid] += v;
        __syncthreads();
    }
    int run = sums[tid] - s;
    for (int i = 0; i < CH; i++) {
        int idx = base + i;
        if (idx < N_NODES) { rowStart[idx] = run; run += deg[idx]; }
    }
    if (tid == 1023) rowStart[N_NODES] = run;
}

__global__ __launch_bounds__(256) void scatter_kernel(
    const int* __restrict__ src, const int* __restrict__ dst,
    const int* __restrict__ rowStart, int* __restrict__ cursor,
    int* __restrict__ sortedSrc, int E)
{
    int i = blockIdx.x * blockDim.x + threadIdx.x;
    if (i >= E) return;
    int d = __ldg(dst + i);
    int pos = __ldg(rowStart + d) + atomicAdd(&cursor[d], 1);
    sortedSrc[pos] = __ldg(src + i);
}

// ---------------------------------------------------------------------------
// GEMM: Yh = half(relu(A[M,256] @ W[256,256] + bias)).
// BM=128, BN=128, BK=8, 256 threads, 8x8 per-thread tile. fp32 math.
// ---------------------------------------------------------------------------
__global__ __launch_bounds__(256) void gemm_bias_relu_h(
    const float* __restrict__ A, const float* __restrict__ W,
    const float* __restrict__ bias, __half* __restrict__ Y)
{
    __shared__ float As[8][128];
    __shared__ float Ws[8][128];

    const int tid = threadIdx.x;
    const int tx = tid & 15;
    const int ty = tid >> 4;
    const int rowBase = blockIdx.y * 128;
    const int colBase = blockIdx.x * 128;

    float acc[8][8];
#pragma unroll
    for (int i = 0; i < 8; i++)
#pragma unroll
        for (int j = 0; j < 8; j++) acc[i][j] = 0.0f;

    for (int k0 = 0; k0 < FDIM; k0 += 8) {
        {
            int r  = tid >> 1;
            int c4 = (tid & 1) * 4;
            float4 v = make_float4(0.f, 0.f, 0.f, 0.f);
            int gr = rowBase + r;
            if (gr < N_NODES)
                v = *(const float4*)(A + (size_t)gr * FDIM + k0 + c4);
            As[c4 + 0][r] = v.x;
            As[c4 + 1][r] = v.y;
            As[c4 + 2][r] = v.z;
            As[c4 + 3][r] = v.w;
        }
        {
            int r  = tid >> 5;
            int c4 = (tid & 31) * 4;
            *(float4*)&Ws[r][c4] =
                *(const float4*)(W + (size_t)(k0 + r) * FDIM + colBase + c4);
        }
        __syncthreads();

#pragma unroll
        for (int k = 0; k < 8; k++) {
            float4 a0 = *(const float4*)&As[k][ty * 8];
            float4 a1 = *(const float4*)&As[k][ty * 8 + 4];
            float4 w0 = *(const float4*)&Ws[k][tx * 8];
            float4 w1 = *(const float4*)&Ws[k][tx * 8 + 4];
            float av[8] = {a0.x, a0.y, a0.z, a0.w, a1.x, a1.y, a1.z, a1.w};
            float wv[8] = {w0.x, w0.y, w0.z, w0.w, w1.x, w1.y, w1.z, w1.w};
#pragma unroll
            for (int i = 0; i < 8; i++)
#pragma unroll
                for (int j = 0; j < 8; j++)
                    acc[i][j] = fmaf(av[i], wv[j], acc[i][j]);
        }
        __syncthreads();
    }

    float b[8];
#pragma unroll
    for (int j = 0; j < 8; j++) b[j] = bias[colBase + tx * 8 + j];

#pragma unroll
    for (int i = 0; i < 8; i++) {
        int gr = rowBase + ty * 8 + i;
        if (gr < N_NODES) {
            __half2 p[4];
#pragma unroll
            for (int j = 0; j < 4; j++) {
                float lo = fmaxf(acc[i][2 * j]     + b[2 * j],     0.f);
                float hi = fmaxf(acc[i][2 * j + 1] + b[2 * j + 1], 0.f);
                p[j] = __floats2half2_rn(lo, hi);
            }
            uint4 st;
            st.x = *(unsigned*)&p[0];
            st.y = *(unsigned*)&p[1];
            st.z = *(unsigned*)&p[2];
            st.w = *(unsigned*)&p[3];
            *(uint4*)(Y + (size_t)gr * FDIM + colBase + tx * 8) = st;
        }
    }
}

// ---------------------------------------------------------------------------
// CSR gather aggregation (fp16 rows -> fp32 accumulate):
// H[v] = Y[v] + sum_{e in CSR(v)} Y[src]. One warp per dst node.
// Row = 512 B; each lane owns 8 halves (one uint4).
// ---------------------------------------------------------------------------
__device__ __forceinline__ void hacc8(float* acc, uint4 v)
{
    float2 f0 = __half22float2(*reinterpret_cast<__half2*>(&v.x));
    float2 f1 = __half22float2(*reinterpret_cast<__half2*>(&v.y));
    float2 f2 = __half22float2(*reinterpret_cast<__half2*>(&v.z));
    float2 f3 = __half22float2(*reinterpret_cast<__half2*>(&v.w));
    acc[0] += f0.x; acc[1] += f0.y;
    acc[2] += f1.x; acc[3] += f1.y;
    acc[4] += f2.x; acc[5] += f2.y;
    acc[6] += f3.x; acc[7] += f3.y;
}

__global__ __launch_bounds__(256) void aggregate_csr_h(
    const __half* __restrict__ Y, float* __restrict__ H,
    const int* __restrict__ rowStart, const int* __restrict__ ssrc)
{
    int node = blockIdx.x * 8 + (threadIdx.x >> 5);
    int lane = threadIdx.x & 31;
    if (node >= N_NODES) return;

    const uint4* yb = (const uint4*)Y;     // 8 halves per uint4; 32 per row
    float acc[8];
#pragma unroll
    for (int i = 0; i < 8; i++) acc[i] = 0.0f;

    // self loop
    hacc8(acc, __ldg(yb + (size_t)node * 32 + lane));

    int e    = __ldg(rowStart + node);
    int eEnd = __ldg(rowStart + node + 1);

    for (; e + 4 <= eEnd; e += 4) {
        int s0 = __ldg(ssrc + e);
        int s1 = __ldg(ssrc + e + 1);
        int s2 = __ldg(ssrc + e + 2);
        int s3 = __ldg(ssrc + e + 3);
        uint4 v0 = __ldg(yb + (size_t)s0 * 32 + lane);
        uint4 v1 = __ldg(yb + (size_t)s1 * 32 + lane);
        uint4 v2 = __ldg(yb + (size_t)s2 * 32 + lane);
        uint4 v3 = __ldg(yb + (size_t)s3 * 32 + lane);
        hacc8(acc, v0); hacc8(acc, v1); hacc8(acc, v2); hacc8(acc, v3);
    }
    for (; e < eEnd; e++) {
        int s0 = __ldg(ssrc + e);
        hacc8(acc, __ldg(yb + (size_t)s0 * 32 + lane));
    }

    float* hp = H + (size_t)node * FDIM + lane * 8;
    *(float4*)(hp)     = make_float4(acc[0], acc[1], acc[2], acc[3]);
    *(float4*)(hp + 4) = make_float4(acc[4], acc[5], acc[6], acc[7]);
}

// ---------------------------------------------------------------------------
// FC: logits[N,40] = H[N,256] @ Wfc[256,40] + bfc.
// ---------------------------------------------------------------------------
__global__ __launch_bounds__(256) void fc_kernel(
    const float* __restrict__ Hf, const float* __restrict__ Wfc,
    const float* __restrict__ bfc, float* __restrict__ L)
{
    int c = threadIdx.x & 63;
    int r = blockIdx.x * 4 + (threadIdx.x >> 6);
    if (r >= N_NODES || c >= NCLS) return;
    const float* hr = Hf + (size_t)r * FDIM;
    float acc = __ldg(bfc + c);
#pragma unroll 4
    for (int k = 0; k < FDIM; k += 4) {
        float4 h4 = *(const float4*)(hr + k);
        acc = fmaf(h4.x, __ldg(Wfc + (k + 0) * NCLS + c), acc);
        acc = fmaf(h4.y, __ldg(Wfc + (k + 1) * NCLS + c), acc);
        acc = fmaf(h4.z, __ldg(Wfc + (k + 2) * NCLS + c), acc);
        acc = fmaf(h4.w, __ldg(Wfc + (k + 3) * NCLS + c), acc);
    }
    L[(size_t)r * NCLS + c] = acc;
}

__global__ __launch_bounds__(256) void zero_f32(float* __restrict__ p, int n)
{
    int i = blockIdx.x * blockDim.x + threadIdx.x;
    if (i < n) p[i] = 0.0f;
}

// ---------------------------------------------------------------------------
// Sparse PvT: Agg[row] += val * logits[col]. One warp per nonzero.
// ---------------------------------------------------------------------------
__global__ __launch_bounds__(256) void pvt_kernel(
    const float* __restrict__ L, float* __restrict__ Agg,
    const int* __restrict__ row, const int* __restrict__ col,
    const float* __restrict__ val, int nnz)
{
    int w    = (blockIdx.x * blockDim.x + threadIdx.x) >> 5;
    int lane = threadIdx.x & 31;
    if (w >= nnz) return;
    int   r = __ldg(row + w);
    int   c = __ldg(col + w);
    float v = __ldg(val + w);
    const float* lr = L + (size_t)c * NCLS;
    float*       ar = Agg + (size_t)r * NCLS;
    atomicAdd(ar + lane, v * __ldg(lr + lane));
    if (lane < 8)
        atomicAdd(ar + 32 + lane, v * __ldg(lr + 32 + lane));
}

// ---------------------------------------------------------------------------
// Row-wise log-softmax over 40 classes. One warp per row.
// ---------------------------------------------------------------------------
__global__ __launch_bounds__(256) void logsoftmax_kernel(
    const float* __restrict__ Agg, float* __restrict__ out)
{
    int w    = (blockIdx.x * blockDim.x + threadIdx.x) >> 5;
    int lane = threadIdx.x & 31;
    if (w >= N_NODES) return;
    const float* a = Agg + (size_t)w * NCLS;
    float x0 = a[lane];
    float x1 = (lane < 8) ? a[32 + lane] : -INFINITY;
    float m = fmaxf(x0, x1);
#pragma unroll
    for (int off = 16; off > 0; off >>= 1)
        m = fmaxf(m, __shfl_xor_sync(0xffffffffu, m, off));
    float e = __expf(x0 - m) + ((lane < 8) ? __expf(x1 - m) : 0.0f);
#pragma unroll
    for (int off = 16; off > 0; off >>= 1)
        e += __shfl_xor_sync(0xffffffffu, e, off);
    float ls = logf(e);
    float* o = out + (size_t)w * NCLS;
    o[lane] = x0 - m - ls;
    if (lane < 8) o[32 + lane] = x1 - m - ls;
}

// ---------------------------------------------------------------------------
extern "C" void kernel_launch(void* const* d_in, const int* in_sizes, int n_in,
                              void* d_out, int out_size)
{
    const float* x    = (const float*)d_in[0];
    const int*   esrc = (const int*)  d_in[1];
    const int*   edst = (const int*)  d_in[2];
    const int*   prow = (const int*)  d_in[3];
    const int*   pcol = (const int*)  d_in[4];
    const float* pval = (const float*)d_in[5];
    const float* w1   = (const float*)d_in[6];
    const float* b1   = (const float*)d_in[7];
    const float* w2   = (const float*)d_in[8];
    const float* b2   = (const float*)d_in[9];
    const float* wfc  = (const float*)d_in[10];
    const float* bfc  = (const float*)d_in[11];
    const int E   = in_sizes[1];
    const int nnz = in_sizes[3];

    __half* Yh;
    float *h1, *h2, *logits, *agg;
    int *ssrc, *rowStart, *deg, *cursor;
    cudaGetSymbolAddress((void**)&Yh,       g_Yh);
    cudaGetSymbolAddress((void**)&h1,       g_h1);
    cudaGetSymbolAddress((void**)&h2,       g_h2);
    cudaGetSymbolAddress((void**)&logits,   g_logits);
    cudaGetSymbolAddress((void**)&agg,      g_agg);
    cudaGetSymbolAddress((void**)&ssrc,     g_sortedSrc);
    cudaGetSymbolAddress((void**)&rowStart, g_rowStart);
    cudaGetSymbolAddress((void**)&deg,      g_deg);
    cudaGetSymbolAddress((void**)&cursor,   g_cursor);

    // --- CSR build (dst-sorted edge list), reused by both convs ---
    zero2_i32<<<(N_NODES + 255) / 256, 256>>>(deg, cursor, N_NODES);
    hist_kernel<<<(E + 255) / 256, 256>>>(edst, deg, E);
    scan_kernel<<<1, 1024>>>(deg, rowStart);
    scatter_kernel<<<(E + 255) / 256, 256>>>(esrc, edst, rowStart, cursor,
                                             ssrc, E);

    dim3 gemm_grid(FDIM / 128, (N_NODES + 127) / 128);
    int  agg_blocks = (N_NODES + 7) / 8;

    // conv1
    gemm_bias_relu_h<<<gemm_grid, 256>>>(x, w1, b1, Yh);
    aggregate_csr_h<<<agg_blocks, 256>>>(Yh, h1, rowStart, ssrc);

    // conv2
    gemm_bias_relu_h<<<gemm_grid, 256>>>(h1, w2, b2, Yh);
    aggregate_csr_h<<<agg_blocks, 256>>>(Yh, h2, rowStart, ssrc);

    // classifier head
    fc_kernel<<<(N_NODES + 3) / 4, 256>>>(h2, wfc, bfc, logits);

    zero_f32<<<(N_NODES * NCLS + 255) / 256, 256>>>(agg, N_NODES * NCLS);
    pvt_kernel<<<(int)(((long long)nnz * 32 + 255) / 256), 256>>>(
        logits, agg, prow, pcol, pval, nnz);

    logsoftmax_kernel<<<(int)(((long long)N_NODES * 32 + 255) / 256), 256>>>(
        agg, (float*)d_out);
}

// round 6
// speedup vs baseline: 2.6754x; 1.7702x over previous
#include <cuda_runtime.h>
#include <cuda_fp16.h>
#include <math.h>

#define N_NODES 50000
#define FDIM    256
#define NCLS    40
#define MAX_E   1700000
#define SP      40          // smem row stride in halves (conflict-free for frags)

// Scratch (device globals only — no runtime allocation)
__device__ __half g_xh [(size_t)N_NODES * FDIM];   // x in fp16
__device__ __half g_Yh [(size_t)N_NODES * FDIM];   // GEMM out (gather source)
__device__ __half g_h1h[(size_t)N_NODES * FDIM];   // conv1 aggregate
__device__ __half g_h2h[(size_t)N_NODES * FDIM];   // conv2 aggregate
__device__ __half g_w1t[FDIM * FDIM];              // W1^T fp16 [n][k]
__device__ __half g_w2t[FDIM * FDIM];              // W2^T fp16 [n][k]
__device__ float  g_logits[(size_t)N_NODES * NCLS];
__device__ float  g_agg[(size_t)N_NODES * NCLS];
__device__ int    g_sortedSrc[MAX_E];
__device__ int    g_rowStart[N_NODES + 1];
__device__ int    g_deg[N_NODES];
__device__ int    g_cursor[N_NODES];

// ---------------------------------------------------------------------------
// Converts
// ---------------------------------------------------------------------------
__global__ __launch_bounds__(256) void f2h_kernel(
    const float4* __restrict__ in, uint2* __restrict__ out, int n4)
{
    int i = blockIdx.x * 256 + threadIdx.x;
    if (i >= n4) return;
    float4 v = __ldg(in + i);
    __half2 lo = __floats2half2_rn(v.x, v.y);
    __half2 hi = __floats2half2_rn(v.z, v.w);
    out[i] = make_uint2(*(unsigned*)&lo, *(unsigned*)&hi);
}

// Wt[n][k] = half(W[k][n])  (256x256)
__global__ __launch_bounds__(256) void wconv_kernel(
    const float* __restrict__ W, __half* __restrict__ Wt)
{
    int n = blockIdx.x;
    int k = threadIdx.x;
    Wt[n * FDIM + k] = __float2half(__ldg(W + k * FDIM + n));
}

// ---------------------------------------------------------------------------
// CSR build: histogram by dst, exclusive scan, scatter of src ids.
// ---------------------------------------------------------------------------
__global__ __launch_bounds__(256) void zero2_i32(int* __restrict__ a,
                                                 int* __restrict__ b, int n)
{
    int i = blockIdx.x * blockDim.x + threadIdx.x;
    if (i < n) { a[i] = 0; b[i] = 0; }
}

__global__ __launch_bounds__(256) void hist_kernel(
    const int* __restrict__ dst, int* __restrict__ deg, int E)
{
    int i = blockIdx.x * blockDim.x + threadIdx.x;
    if (i < E) atomicAdd(&deg[__ldg(dst + i)], 1);
}

__global__ __launch_bounds__(1024) void scan_kernel(
    const int* __restrict__ deg, int* __restrict__ rowStart)
{
    __shared__ int sums[1024];
    const int tid = threadIdx.x;
    const int CH  = (N_NODES + 1023) / 1024;
    const int base = tid * CH;
    int s = 0;
    for (int i = 0; i < CH; i++) {
        int idx = base + i;
        if (idx < N_NODES) s += deg[idx];
    }
    sums[tid] = s;
    __syncthreads();
    for (int off = 1; off < 1024; off <<= 1) {
        int v = (tid >= off) ? sums[tid - off] : 0;
        __syncthreads();
        sums[tid] += v;
        __syncthreads();
    }
    int run = sums[tid] - s;
    for (int i = 0; i < CH; i++) {
        int idx = base + i;
        if (idx < N_NODES) { rowStart[idx] = run; run += deg[idx]; }
    }
    if (tid == 1023) rowStart[N_NODES] = run;
}

__global__ __launch_bounds__(256) void scatter_kernel(
    const int* __restrict__ src, const int* __restrict__ dst,
    const int* __restrict__ rowStart, int* __restrict__ cursor,
    int* __restrict__ sortedSrc, int E)
{
    int i = blockIdx.x * blockDim.x + threadIdx.x;
    if (i >= E) return;
    int d = __ldg(dst + i);
    int pos = __ldg(rowStart + d) + atomicAdd(&cursor[d], 1);
    sortedSrc[pos] = __ldg(src + i);
}

// ---------------------------------------------------------------------------
// Tensor-core GEMM: Y = half(relu(A[M,256] @ W[256,256] + bias)).
// A fp16 row-major, Wt fp16 [n][k]. BM=BN=128, BK=32, 8 warps.
// mma.sync.m16n8k16 fp16->fp32. Warp tile 32x64 (2 mfrag x 8 nfrag).
// ---------------------------------------------------------------------------
__device__ __forceinline__ void mma_16816(float c[4], const unsigned a[4],
                                          const unsigned b[2])
{
    asm volatile(
        "mma.sync.aligned.m16n8k16.row.col.f32.f16.f16.f32 "
        "{%0,%1,%2,%3}, {%4,%5,%6,%7}, {%8,%9}, {%0,%1,%2,%3};\n"
        : "+f"(c[0]), "+f"(c[1]), "+f"(c[2]), "+f"(c[3])
        : "r"(a[0]), "r"(a[1]), "r"(a[2]), "r"(a[3]), "r"(b[0]), "r"(b[1]));
}

__global__ __launch_bounds__(256, 2) void gemm_mma(
    const __half* __restrict__ A, const __half* __restrict__ Wt,
    const float* __restrict__ bias, __half* __restrict__ Y)
{
    __shared__ __half As[128 * SP];
    __shared__ __half Bs[128 * SP];

    const int tid   = threadIdx.x;
    const int wid   = tid >> 5;
    const int lane  = tid & 31;
    const int gid   = lane >> 2;
    const int tig   = lane & 3;
    const int warp_m = wid & 3;    // 0..3 -> 32 rows each
    const int warp_n = wid >> 2;   // 0..1 -> 64 cols each
    const int rowBase = blockIdx.y * 128;
    const int colBase = blockIdx.x * 128;

    float acc[2][8][4];
#pragma unroll
    for (int mf = 0; mf < 2; mf++)
#pragma unroll
        for (int nf = 0; nf < 8; nf++)
#pragma unroll
            for (int j = 0; j < 4; j++) acc[mf][nf][j] = 0.0f;

    for (int k0 = 0; k0 < FDIM; k0 += 32) {
#pragma unroll
        for (int i = 0; i < 2; i++) {
            int idx = tid + i * 256;
            int r   = idx >> 2;
            int cg  = idx & 3;
            uint4 va = make_uint4(0u, 0u, 0u, 0u);
            int gr = rowBase + r;
            if (gr < N_NODES)
                va = *(const uint4*)(A + (size_t)gr * FDIM + k0 + cg * 8);
            *(uint4*)&As[r * SP + cg * 8] = va;
            uint4 vb = *(const uint4*)(Wt + (size_t)(colBase + r) * FDIM + k0 + cg * 8);
            *(uint4*)&Bs[r * SP + cg * 8] = vb;
        }
        __syncthreads();

#pragma unroll
        for (int ks = 0; ks < 2; ks++) {
            const int kk = ks * 16 + tig * 2;
            unsigned af[2][4];
#pragma unroll
            for (int mf = 0; mf < 2; mf++) {
                int r0 = warp_m * 32 + mf * 16 + gid;
                af[mf][0] = *(const unsigned*)&As[(r0    ) * SP + kk];
                af[mf][1] = *(const unsigned*)&As[(r0 + 8) * SP + kk];
                af[mf][2] = *(const unsigned*)&As[(r0    ) * SP + kk + 8];
                af[mf][3] = *(const unsigned*)&As[(r0 + 8) * SP + kk + 8];
            }
#pragma unroll
            for (int nf = 0; nf < 8; nf++) {
                int c0 = warp_n * 64 + nf * 8 + gid;
                unsigned bf[2];
                bf[0] = *(const unsigned*)&Bs[c0 * SP + kk];
                bf[1] = *(const unsigned*)&Bs[c0 * SP + kk + 8];
                mma_16816(acc[0][nf], af[0], bf);
                mma_16816(acc[1][nf], af[1], bf);
            }
        }
        __syncthreads();
    }

    // epilogue: bias + relu + fp16 store
    float2 bv[8];
#pragma unroll
    for (int nf = 0; nf < 8; nf++)
        bv[nf] = *(const float2*)(bias + colBase + warp_n * 64 + nf * 8 + tig * 2);

#pragma unroll
    for (int mf = 0; mf < 2; mf++) {
        int gr0 = rowBase + warp_m * 32 + mf * 16 + gid;
        int gr1 = gr0 + 8;
#pragma unroll
        for (int nf = 0; nf < 8; nf++) {
            int col = colBase + warp_n * 64 + nf * 8 + tig * 2;
            if (gr0 < N_NODES) {
                __half2 h = __floats2half2_rn(
                    fmaxf(acc[mf][nf][0] + bv[nf].x, 0.f),
                    fmaxf(acc[mf][nf][1] + bv[nf].y, 0.f));
                *(__half2*)(Y + (size_t)gr0 * FDIM + col) = h;
            }
            if (gr1 < N_NODES) {
                __half2 h = __floats2half2_rn(
                    fmaxf(acc[mf][nf][2] + bv[nf].x, 0.f),
                    fmaxf(acc[mf][nf][3] + bv[nf].y, 0.f));
                *(__half2*)(Y + (size_t)gr1 * FDIM + col) = h;
            }
        }
    }
}

// ---------------------------------------------------------------------------
// CSR gather aggregation (fp16 rows -> fp32 accumulate -> fp16 store):
// H[v] = Y[v] + sum_{e in CSR(v)} Y[src]. One warp per dst node.
// ---------------------------------------------------------------------------
__device__ __forceinline__ void hacc8(float* acc, uint4 v)
{
    float2 f0 = __half22float2(*reinterpret_cast<__half2*>(&v.x));
    float2 f1 = __half22float2(*reinterpret_cast<__half2*>(&v.y));
    float2 f2 = __half22float2(*reinterpret_cast<__half2*>(&v.z));
    float2 f3 = __half22float2(*reinterpret_cast<__half2*>(&v.w));
    acc[0] += f0.x; acc[1] += f0.y;
    acc[2] += f1.x; acc[3] += f1.y;
    acc[4] += f2.x; acc[5] += f2.y;
    acc[6] += f3.x; acc[7] += f3.y;
}

__global__ __launch_bounds__(256) void aggregate_csr_h(
    const __half* __restrict__ Y, __half* __restrict__ H,
    const int* __restrict__ rowStart, const int* __restrict__ ssrc)
{
    int node = blockIdx.x * 8 + (threadIdx.x >> 5);
    int lane = threadIdx.x & 31;
    if (node >= N_NODES) return;

    const uint4* yb = (const uint4*)Y;     // 8 halves per uint4; 32 per row
    float acc[8];
#pragma unroll
    for (int i = 0; i < 8; i++) acc[i] = 0.0f;

    hacc8(acc, __ldg(yb + (size_t)node * 32 + lane));   // self loop

    int e    = __ldg(rowStart + node);
    int eEnd = __ldg(rowStart + node + 1);

    for (; e + 4 <= eEnd; e += 4) {
        int s0 = __ldg(ssrc + e);
        int s1 = __ldg(ssrc + e + 1);
        int s2 = __ldg(ssrc + e + 2);
        int s3 = __ldg(ssrc + e + 3);
        uint4 v0 = __ldg(yb + (size_t)s0 * 32 + lane);
        uint4 v1 = __ldg(yb + (size_t)s1 * 32 + lane);
        uint4 v2 = __ldg(yb + (size_t)s2 * 32 + lane);
        uint4 v3 = __ldg(yb + (size_t)s3 * 32 + lane);
        hacc8(acc, v0); hacc8(acc, v1); hacc8(acc, v2); hacc8(acc, v3);
    }
    for (; e < eEnd; e++) {
        int s0 = __ldg(ssrc + e);
        hacc8(acc, __ldg(yb + (size_t)s0 * 32 + lane));
    }

    __half2 o0 = __floats2half2_rn(acc[0], acc[1]);
    __half2 o1 = __floats2half2_rn(acc[2], acc[3]);
    __half2 o2 = __floats2half2_rn(acc[4], acc[5]);
    __half2 o3 = __floats2half2_rn(acc[6], acc[7]);
    uint4 st;
    st.x = *(unsigned*)&o0; st.y = *(unsigned*)&o1;
    st.z = *(unsigned*)&o2; st.w = *(unsigned*)&o3;
    *(uint4*)(H + (size_t)node * FDIM + lane * 8) = st;
}

// ---------------------------------------------------------------------------
// FC: logits[N,40] = H[N,256](fp16) @ Wfc[256,40] + bfc.
// ---------------------------------------------------------------------------
__global__ __launch_bounds__(256) void fc_kernel(
    const __half* __restrict__ Hf, const float* __restrict__ Wfc,
    const float* __restrict__ bfc, float* __restrict__ L)
{
    int c = threadIdx.x & 63;
    int r = blockIdx.x * 4 + (threadIdx.x >> 6);
    if (r >= N_NODES || c >= NCLS) return;
    const __half2* hr = (const __half2*)(Hf + (size_t)r * FDIM);
    float acc = __ldg(bfc + c);
#pragma unroll 8
    for (int k2 = 0; k2 < FDIM / 2; k2++) {
        float2 h2 = __half22float2(hr[k2]);
        acc = fmaf(h2.x, __ldg(Wfc + (2 * k2    ) * NCLS + c), acc);
        acc = fmaf(h2.y, __ldg(Wfc + (2 * k2 + 1) * NCLS + c), acc);
    }
    L[(size_t)r * NCLS + c] = acc;
}

__global__ __launch_bounds__(256) void zero_f32(float* __restrict__ p, int n)
{
    int i = blockIdx.x * blockDim.x + threadIdx.x;
    if (i < n) p[i] = 0.0f;
}

// ---------------------------------------------------------------------------
// Sparse PvT: Agg[row] += val * logits[col]. One warp per nonzero.
// ---------------------------------------------------------------------------
__global__ __launch_bounds__(256) void pvt_kernel(
    const float* __restrict__ L, float* __restrict__ Agg,
    const int* __restrict__ row, const int* __restrict__ col,
    const float* __restrict__ val, int nnz)
{
    int w    = (blockIdx.x * blockDim.x + threadIdx.x) >> 5;
    int lane = threadIdx.x & 31;
    if (w >= nnz) return;
    int   r = __ldg(row + w);
    int   c = __ldg(col + w);
    float v = __ldg(val + w);
    const float* lr = L + (size_t)c * NCLS;
    float*       ar = Agg + (size_t)r * NCLS;
    atomicAdd(ar + lane, v * __ldg(lr + lane));
    if (lane < 8)
        atomicAdd(ar + 32 + lane, v * __ldg(lr + 32 + lane));
}

// ---------------------------------------------------------------------------
// Row-wise log-softmax over 40 classes. One warp per row.
// ---------------------------------------------------------------------------
__global__ __launch_bounds__(256) void logsoftmax_kernel(
    const float* __restrict__ Agg, float* __restrict__ out)
{
    int w    = (blockIdx.x * blockDim.x + threadIdx.x) >> 5;
    int lane = threadIdx.x & 31;
    if (w >= N_NODES) return;
    const float* a = Agg + (size_t)w * NCLS;
    float x0 = a[lane];
    float x1 = (lane < 8) ? a[32 + lane] : -INFINITY;
    float m = fmaxf(x0, x1);
#pragma unroll
    for (int off = 16; off > 0; off >>= 1)
        m = fmaxf(m, __shfl_xor_sync(0xffffffffu, m, off));
    float e = __expf(x0 - m) + ((lane < 8) ? __expf(x1 - m) : 0.0f);
#pragma unroll
    for (int off = 16; off > 0; off >>= 1)
        e += __shfl_xor_sync(0xffffffffu, e, off);
    float ls = logf(e);
    float* o = out + (size_t)w * NCLS;
    o[lane] = x0 - m - ls;
    if (lane < 8) o[32 + lane] = x1 - m - ls;
}

// ---------------------------------------------------------------------------
extern "C" void kernel_launch(void* const* d_in, const int* in_sizes, int n_in,
                              void* d_out, int out_size)
{
    const float* x    = (const float*)d_in[0];
    const int*   esrc = (const int*)  d_in[1];
    const int*   edst = (const int*)  d_in[2];
    const int*   prow = (const int*)  d_in[3];
    const int*   pcol = (const int*)  d_in[4];
    const float* pval = (const float*)d_in[5];
    const float* w1   = (const float*)d_in[6];
    const float* b1   = (const float*)d_in[7];
    const float* w2   = (const float*)d_in[8];
    const float* b2   = (const float*)d_in[9];
    const float* wfc  = (const float*)d_in[10];
    const float* bfc  = (const float*)d_in[11];
    const int E   = in_sizes[1];
    const int nnz = in_sizes[3];

    __half *xh, *Yh, *h1h, *h2h, *w1t, *w2t;
    float *logits, *agg;
    int *ssrc, *rowStart, *deg, *cursor;
    cudaGetSymbolAddress((void**)&xh,       g_xh);
    cudaGetSymbolAddress((void**)&Yh,       g_Yh);
    cudaGetSymbolAddress((void**)&h1h,      g_h1h);
    cudaGetSymbolAddress((void**)&h2h,      g_h2h);
    cudaGetSymbolAddress((void**)&w1t,      g_w1t);
    cudaGetSymbolAddress((void**)&w2t,      g_w2t);
    cudaGetSymbolAddress((void**)&logits,   g_logits);
    cudaGetSymbolAddress((void**)&agg,      g_agg);
    cudaGetSymbolAddress((void**)&ssrc,     g_sortedSrc);
    cudaGetSymbolAddress((void**)&rowStart, g_rowStart);
    cudaGetSymbolAddress((void**)&deg,      g_deg);
    cudaGetSymbolAddress((void**)&cursor,   g_cursor);

    // Lazily created side stream + events (host-side only; capture-legal
    // fork/join pattern — all side work joins before dependent main work).
    static cudaStream_t side = nullptr;
    static cudaEvent_t evFork = nullptr, evJoin = nullptr;
    if (!side) {
        cudaStreamCreateWithFlags(&side, cudaStreamNonBlocking);
        cudaEventCreateWithFlags(&evFork, cudaEventDisableTiming);
        cudaEventCreateWithFlags(&evJoin, cudaEventDisableTiming);
    }

    // --- fork: CSR build + agg-zero on side stream ---
    cudaEventRecord(evFork, 0);
    cudaStreamWaitEvent(side, evFork, 0);
    zero2_i32<<<(N_NODES + 255) / 256, 256, 0, side>>>(deg, cursor, N_NODES);
    hist_kernel<<<(E + 255) / 256, 256, 0, side>>>(edst, deg, E);
    scan_kernel<<<1, 1024, 0, side>>>(deg, rowStart);
    scatter_kernel<<<(E + 255) / 256, 256, 0, side>>>(esrc, edst, rowStart,
                                                      cursor, ssrc, E);
    zero_f32<<<(N_NODES * NCLS + 255) / 256, 256, 0, side>>>(agg,
                                                             N_NODES * NCLS);
    cudaEventRecord(evJoin, side);

    // --- main stream: converts + conv1 GEMM (independent of CSR) ---
    f2h_kernel<<<(N_NODES * FDIM / 4 + 255) / 256, 256>>>(
        (const float4*)x, (uint2*)xh, N_NODES * FDIM / 4);
    wconv_kernel<<<FDIM, FDIM>>>(w1, w1t);
    wconv_kernel<<<FDIM, FDIM>>>(w2, w2t);

    dim3 gemm_grid(FDIM / 128, (N_NODES + 127) / 128);
    int  agg_blocks = (N_NODES + 7) / 8;

    gemm_mma<<<gemm_grid, 256>>>(xh, w1t, b1, Yh);

    // join: aggregation needs the CSR
    cudaStreamWaitEvent(0, evJoin, 0);
    aggregate_csr_h<<<agg_blocks, 256>>>(Yh, h1h, rowStart, ssrc);

    // conv2
    gemm_mma<<<gemm_grid, 256>>>(h1h, w2t, b2, Yh);
    aggregate_csr_h<<<agg_blocks, 256>>>(Yh, h2h, rowStart, ssrc);

    // classifier head
    fc_kernel<<<(N_NODES + 3) / 4, 256>>>(h2h, wfc, bfc, logits);
    pvt_kernel<<<(int)(((long long)nnz * 32 + 255) / 256), 256>>>(
        logits, agg, prow, pcol, pval, nnz);
    logsoftmax_kernel<<<(int)(((long long)N_NODES * 32 + 255) / 256), 256>>>(
        agg, (float*)d_out);
}

// round 9
// speedup vs baseline: 3.9106x; 1.4617x over previous
#include <cuda_runtime.h>
#include <cuda_fp16.h>
#include <math.h>

#define N_NODES 50000
#define FDIM    256
#define NCLS    40
#define NPAD    64
#define MAX_E   1700000
#define SP      40          // smem row stride in halves (conflict-free frags)
#define CHUNK_ROWS 12544    // 98 * 128
#define NCHUNK  4

// Scratch (device globals only — no runtime allocation)
__device__ __half g_Y1h[(size_t)N_NODES * FDIM];   // conv1 GEMM out
__device__ __half g_Y2h[(size_t)N_NODES * FDIM];   // conv2 GEMM out
__device__ __half g_h1h[(size_t)N_NODES * FDIM];   // conv1 aggregate
__device__ __half g_h2h[(size_t)N_NODES * FDIM];   // conv2 aggregate
__device__ __half g_w1t[FDIM * FDIM];              // W1^T fp16 [n][k]
__device__ __half g_w2t[FDIM * FDIM];              // W2^T fp16 [n][k]
__device__ __half g_wfct[NPAD * FDIM];             // Wfc^T fp16 [n][k], padded
__device__ float  g_bfcp[NPAD];
__device__ float  g_logits[(size_t)N_NODES * NCLS];
__device__ float  g_agg[(size_t)N_NODES * NCLS];
__device__ int    g_sortedSrc[MAX_E];
__device__ int    g_rowStart[N_NODES + 1];
__device__ int    g_deg[N_NODES];
__device__ int    g_cursor[N_NODES];

// ---------------------------------------------------------------------------
// Weight converts
// ---------------------------------------------------------------------------
__global__ __launch_bounds__(256) void wconv_kernel(
    const float* __restrict__ W, __half* __restrict__ Wt)
{
    int n = blockIdx.x;
    int k = threadIdx.x;
    Wt[n * FDIM + k] = __float2half(__ldg(W + k * FDIM + n));
}

__global__ __launch_bounds__(256) void wfc_conv_kernel(
    const float* __restrict__ Wfc, __half* __restrict__ Wt)
{
    int n = blockIdx.x;           // 0..63
    int k = threadIdx.x;
    Wt[n * FDIM + k] = (n < NCLS) ? __float2half(__ldg(Wfc + k * NCLS + n))
                                  : __float2half(0.0f);
}

__global__ __launch_bounds__(64) void bfc_pad_kernel(
    const float* __restrict__ bfc, float* __restrict__ bp)
{
    int i = threadIdx.x;
    bp[i] = (i < NCLS) ? __ldg(bfc + i) : 0.0f;
}

// ---------------------------------------------------------------------------
// CSR build
// ---------------------------------------------------------------------------
__global__ __launch_bounds__(256) void zero2_i32(int* __restrict__ a,
                                                 int* __restrict__ b, int n)
{
    int i = blockIdx.x * blockDim.x + threadIdx.x;
    if (i < n) { a[i] = 0; b[i] = 0; }
}

__global__ __launch_bounds__(256) void hist_kernel(
    const int* __restrict__ dst, int* __restrict__ deg, int E)
{
    int i = blockIdx.x * blockDim.x + threadIdx.x;
    if (i < E) atomicAdd(&deg[__ldg(dst + i)], 1);
}

__global__ __launch_bounds__(1024) void scan_kernel(
    const int* __restrict__ deg, int* __restrict__ rowStart)
{
    __shared__ int sums[1024];
    const int tid = threadIdx.x;
    const int CH  = (N_NODES + 1023) / 1024;
    const int base = tid * CH;
    int s = 0;
    for (int i = 0; i < CH; i++) {
        int idx = base + i;
        if (idx < N_NODES) s += deg[idx];
    }
    sums[tid] = s;
    __syncthreads();
    for (int off = 1; off < 1024; off <<= 1) {
        int v = (tid >= off) ? sums[tid - off] : 0;
        __syncthreads();
        sums[tid] += v;
        __syncthreads();
    }
    int run = sums[tid] - s;
    for (int i = 0; i < CH; i++) {
        int idx = base + i;
        if (idx < N_NODES) { rowStart[idx] = run; run += deg[idx]; }
    }
    if (tid == 1023) rowStart[N_NODES] = run;
}

__global__ __launch_bounds__(256) void scatter_kernel(
    const int* __restrict__ src, const int* __restrict__ dst,
    const int* __restrict__ rowStart, int* __restrict__ cursor,
    int* __restrict__ sortedSrc, int E)
{
    int i = blockIdx.x * blockDim.x + threadIdx.x;
    if (i >= E) return;
    int d = __ldg(dst + i);
    int pos = __ldg(rowStart + d) + atomicAdd(&cursor[d], 1);
    sortedSrc[pos] = __ldg(src + i);
}

// ---------------------------------------------------------------------------
// Tensor-core GEMM: Y = half(relu(A[M,256] @ W[256,256] + bias)).
// A fp16 or fp32 row-major (templated), Wt fp16 [n][k].
// BM=BN=128, BK=32, 8 warps. mma.sync.m16n8k16 fp16->fp32.
// ---------------------------------------------------------------------------
__device__ __forceinline__ void mma_16816(float c[4], const unsigned a[4],
                                          const unsigned b[2])
{
    asm volatile(
        "mma.sync.aligned.m16n8k16.row.col.f32.f16.f16.f32 "
        "{%0,%1,%2,%3}, {%4,%5,%6,%7}, {%8,%9}, {%0,%1,%2,%3};\n"
        : "+f"(c[0]), "+f"(c[1]), "+f"(c[2]), "+f"(c[3])
        : "r"(a[0]), "r"(a[1]), "r"(a[2]), "r"(a[3]), "r"(b[0]), "r"(b[1]));
}

template <bool A_FP32>
__global__ __launch_bounds__(256, 2) void gemm_mma(
    const void* __restrict__ Av, const __half* __restrict__ Wt,
    const float* __restrict__ bias, __half* __restrict__ Y, int rowOff)
{
    __shared__ __half As[128 * SP];
    __shared__ __half Bs[128 * SP];

    const int tid   = threadIdx.x;
    const int wid   = tid >> 5;
    const int lane  = tid & 31;
    const int gid   = lane >> 2;
    const int tig   = lane & 3;
    const int warp_m = wid & 3;
    const int warp_n = wid >> 2;
    const int rowBase = rowOff + blockIdx.y * 128;
    const int colBase = blockIdx.x * 128;

    float acc[2][8][4];
#pragma unroll
    for (int mf = 0; mf < 2; mf++)
#pragma unroll
        for (int nf = 0; nf < 8; nf++)
#pragma unroll
            for (int j = 0; j < 4; j++) acc[mf][nf][j] = 0.0f;

    for (int k0 = 0; k0 < FDIM; k0 += 32) {
#pragma unroll
        for (int i = 0; i < 2; i++) {
            int idx = tid + i * 256;
            int r   = idx >> 2;
            int cg  = idx & 3;
            int gr  = rowBase + r;
            uint4 va;
            if (A_FP32) {
                float4 f0 = make_float4(0.f, 0.f, 0.f, 0.f);
                float4 f1 = make_float4(0.f, 0.f, 0.f, 0.f);
                if (gr < N_NODES) {
                    const float* ap = (const float*)Av + (size_t)gr * FDIM + k0 + cg * 8;
                    f0 = *(const float4*)ap;
                    f1 = *(const float4*)(ap + 4);
                }
                __half2 h0 = __floats2half2_rn(f0.x, f0.y);
                __half2 h1 = __floats2half2_rn(f0.z, f0.w);
                __half2 h2 = __floats2half2_rn(f1.x, f1.y);
                __half2 h3 = __floats2half2_rn(f1.z, f1.w);
                va = make_uint4(*(unsigned*)&h0, *(unsigned*)&h1,
                                *(unsigned*)&h2, *(unsigned*)&h3);
            } else {
                va = make_uint4(0u, 0u, 0u, 0u);
                if (gr < N_NODES)
                    va = *(const uint4*)((const __half*)Av + (size_t)gr * FDIM + k0 + cg * 8);
            }
            *(uint4*)&As[r * SP + cg * 8] = va;
            uint4 vb = *(const uint4*)(Wt + (size_t)(colBase + r) * FDIM + k0 + cg * 8);
            *(uint4*)&Bs[r * SP + cg * 8] = vb;
        }
        __syncthreads();

#pragma unroll
        for (int ks = 0; ks < 2; ks++) {
            const int kk = ks * 16 + tig * 2;
            unsigned af[2][4];
#pragma unroll
            for (int mf = 0; mf < 2; mf++) {
                int r0 = warp_m * 32 + mf * 16 + gid;
                af[mf][0] = *(const unsigned*)&As[(r0    ) * SP + kk];
                af[mf][1] = *(const unsigned*)&As[(r0 + 8) * SP + kk];
                af[mf][2] = *(const unsigned*)&As[(r0    ) * SP + kk + 8];
                af[mf][3] = *(const unsigned*)&As[(r0 + 8) * SP + kk + 8];
            }
#pragma unroll
            for (int nf = 0; nf < 8; nf++) {
                int c0 = warp_n * 64 + nf * 8 + gid;
                unsigned bf[2];
                bf[0] = *(const unsigned*)&Bs[c0 * SP + kk];
                bf[1] = *(const unsigned*)&Bs[c0 * SP + kk + 8];
                mma_16816(acc[0][nf], af[0], bf);
                mma_16816(acc[1][nf], af[1], bf);
            }
        }
        __syncthreads();
    }

    float2 bv[8];
#pragma unroll
    for (int nf = 0; nf < 8; nf++)
        bv[nf] = *(const float2*)(bias + colBase + warp_n * 64 + nf * 8 + tig * 2);

#pragma unroll
    for (int mf = 0; mf < 2; mf++) {
        int gr0 = rowBase + warp_m * 32 + mf * 16 + gid;
        int gr1 = gr0 + 8;
#pragma unroll
        for (int nf = 0; nf < 8; nf++) {
            int col = colBase + warp_n * 64 + nf * 8 + tig * 2;
            if (gr0 < N_NODES) {
                __half2 h = __floats2half2_rn(
                    fmaxf(acc[mf][nf][0] + bv[nf].x, 0.f),
                    fmaxf(acc[mf][nf][1] + bv[nf].y, 0.f));
                *(__half2*)(Y + (size_t)gr0 * FDIM + col) = h;
            }
            if (gr1 < N_NODES) {
                __half2 h = __floats2half2_rn(
                    fmaxf(acc[mf][nf][2] + bv[nf].x, 0.f),
                    fmaxf(acc[mf][nf][3] + bv[nf].y, 0.f));
                *(__half2*)(Y + (size_t)gr1 * FDIM + col) = h;
            }
        }
    }
}

// ---------------------------------------------------------------------------
// FC via tensor cores: logits[N,40] = h2[N,256](fp16) @ WfcT + bfc (fp32 out).
// BM=128, BN=64(pad), BK=32. 8 warps, warp tile 16x64.
// ---------------------------------------------------------------------------
__global__ __launch_bounds__(256, 2) void fc_mma(
    const __half* __restrict__ A, const __half* __restrict__ Wt,
    const float* __restrict__ bias, float* __restrict__ L)
{
    __shared__ __half As[128 * SP];
    __shared__ __half Bs[64 * SP];

    const int tid  = threadIdx.x;
    const int wid  = tid >> 5;
    const int lane = tid & 31;
    const int gid  = lane >> 2;
    const int tig  = lane & 3;
    const int rowBase = blockIdx.y * 128;

    float acc[8][4];
#pragma unroll
    for (int nf = 0; nf < 8; nf++)
#pragma unroll
        for (int j = 0; j < 4; j++) acc[nf][j] = 0.0f;

    for (int k0 = 0; k0 < FDIM; k0 += 32) {
#pragma unroll
        for (int i = 0; i < 2; i++) {
            int idx = tid + i * 256;
            int r   = idx >> 2;
            int cg  = idx & 3;
            int gr  = rowBase + r;
            uint4 va = make_uint4(0u, 0u, 0u, 0u);
            if (gr < N_NODES)
                va = *(const uint4*)(A + (size_t)gr * FDIM + k0 + cg * 8);
            *(uint4*)&As[r * SP + cg * 8] = va;
        }
        {
            int r  = tid >> 2;          // 0..63
            int cg = tid & 3;
            uint4 vb = *(const uint4*)(Wt + (size_t)r * FDIM + k0 + cg * 8);
            *(uint4*)&Bs[r * SP + cg * 8] = vb;
        }
        __syncthreads();

#pragma unroll
        for (int ks = 0; ks < 2; ks++) {
            const int kk = ks * 16 + tig * 2;
            unsigned af[4];
            int r0 = wid * 16 + gid;
            af[0] = *(const unsigned*)&As[(r0    ) * SP + kk];
            af[1] = *(const unsigned*)&As[(r0 + 8) * SP + kk];
            af[2] = *(const unsigned*)&As[(r0    ) * SP + kk + 8];
            af[3] = *(const unsigned*)&As[(r0 + 8) * SP + kk + 8];
#pragma unroll
            for (int nf = 0; nf < 8; nf++) {
                int c0 = nf * 8 + gid;
                unsigned bf[2];
                bf[0] = *(const unsigned*)&Bs[c0 * SP + kk];
                bf[1] = *(const unsigned*)&Bs[c0 * SP + kk + 8];
                mma_16816(acc[nf], af, bf);
            }
        }
        __syncthreads();
    }

#pragma unroll
    for (int nf = 0; nf < 8; nf++) {
        int c0 = nf * 8 + tig * 2;
        if (c0 >= NCLS) continue;
        float2 bv = *(const float2*)(bias + c0);
        int r0 = rowBase + wid * 16 + gid;
        int r1 = r0 + 8;
        if (r0 < N_NODES)
            *(float2*)(L + (size_t)r0 * NCLS + c0) =
                make_float2(acc[nf][0] + bv.x, acc[nf][1] + bv.y);
        if (r1 < N_NODES)
            *(float2*)(L + (size_t)r1 * NCLS + c0) =
                make_float2(acc[nf][2] + bv.x, acc[nf][3] + bv.y);
    }
}

// ---------------------------------------------------------------------------
// CSR gather aggregation (fp16 -> fp32 acc -> fp16), chunked by node range.
// ---------------------------------------------------------------------------
__device__ __forceinline__ void hacc8(float* acc, uint4 v)
{
    float2 f0 = __half22float2(*reinterpret_cast<__half2*>(&v.x));
    float2 f1 = __half22float2(*reinterpret_cast<__half2*>(&v.y));
    float2 f2 = __half22float2(*reinterpret_cast<__half2*>(&v.z));
    float2 f3 = __half22float2(*reinterpret_cast<__half2*>(&v.w));
    acc[0] += f0.x; acc[1] += f0.y;
    acc[2] += f1.x; acc[3] += f1.y;
    acc[4] += f2.x; acc[5] += f2.y;
    acc[6] += f3.x; acc[7] += f3.y;
}

__global__ __launch_bounds__(256) void aggregate_csr_h(
    const __half* __restrict__ Y, __half* __restrict__ H,
    const int* __restrict__ rowStart, const int* __restrict__ ssrc,
    int nodeOff, int nodeEnd)
{
    int node = nodeOff + blockIdx.x * 8 + (threadIdx.x >> 5);
    int lane = threadIdx.x & 31;
    if (node >= nodeEnd) return;

    const uint4* yb = (const uint4*)Y;
    float acc[8];
#pragma unroll
    for (int i = 0; i < 8; i++) acc[i] = 0.0f;

    hacc8(acc, __ldg(yb + (size_t)node * 32 + lane));   // self loop

    int e    = __ldg(rowStart + node);
    int eEnd = __ldg(rowStart + node + 1);

    for (; e + 4 <= eEnd; e += 4) {
        int s0 = __ldg(ssrc + e);
        int s1 = __ldg(ssrc + e + 1);
        int s2 = __ldg(ssrc + e + 2);
        int s3 = __ldg(ssrc + e + 3);
        uint4 v0 = __ldg(yb + (size_t)s0 * 32 + lane);
        uint4 v1 = __ldg(yb + (size_t)s1 * 32 + lane);
        uint4 v2 = __ldg(yb + (size_t)s2 * 32 + lane);
        uint4 v3 = __ldg(yb + (size_t)s3 * 32 + lane);
        hacc8(acc, v0); hacc8(acc, v1); hacc8(acc, v2); hacc8(acc, v3);
    }
    for (; e < eEnd; e++) {
        int s0 = __ldg(ssrc + e);
        hacc8(acc, __ldg(yb + (size_t)s0 * 32 + lane));
    }

    __half2 o0 = __floats2half2_rn(acc[0], acc[1]);
    __half2 o1 = __floats2half2_rn(acc[2], acc[3]);
    __half2 o2 = __floats2half2_rn(acc[4], acc[5]);
    __half2 o3 = __floats2half2_rn(acc[6], acc[7]);
    uint4 st;
    st.x = *(unsigned*)&o0; st.y = *(unsigned*)&o1;
    st.z = *(unsigned*)&o2; st.w = *(unsigned*)&o3;
    *(uint4*)(H + (size_t)node * FDIM + lane * 8) = st;
}

__global__ __launch_bounds__(256) void zero_f32(float* __restrict__ p, int n)
{
    int i = blockIdx.x * blockDim.x + threadIdx.x;
    if (i < n) p[i] = 0.0f;
}

// ---------------------------------------------------------------------------
// Sparse PvT: Agg[row] += val * logits[col]. One warp per nonzero.
// ---------------------------------------------------------------------------
__global__ __launch_bounds__(256) void pvt_kernel(
    const float* __restrict__ L, float* __restrict__ Agg,
    const int* __restrict__ row, const int* __restrict__ col,
    const float* __restrict__ val, int nnz)
{
    int w    = (blockIdx.x * blockDim.x + threadIdx.x) >> 5;
    int lane = threadIdx.x & 31;
    if (w >= nnz) return;
    int   r = __ldg(row + w);
    int   c = __ldg(col + w);
    float v = __ldg(val + w);
    const float* lr = L + (size_t)c * NCLS;
    float*       ar = Agg + (size_t)r * NCLS;
    atomicAdd(ar + lane, v * __ldg(lr + lane));
    if (lane < 8)
        atomicAdd(ar + 32 + lane, v * __ldg(lr + 32 + lane));
}

// ---------------------------------------------------------------------------
// Row-wise log-softmax over 40 classes. One warp per row.
// ---------------------------------------------------------------------------
__global__ __launch_bounds__(256) void logsoftmax_kernel(
    const float* __restrict__ Agg, float* __restrict__ out)
{
    int w    = (blockIdx.x * blockDim.x + threadIdx.x) >> 5;
    int lane = threadIdx.x & 31;
    if (w >= N_NODES) return;
    const float* a = Agg + (size_t)w * NCLS;
    float x0 = a[lane];
    float x1 = (lane < 8) ? a[32 + lane] : -INFINITY;
    float m = fmaxf(x0, x1);
#pragma unroll
    for (int off = 16; off > 0; off >>= 1)
        m = fmaxf(m, __shfl_xor_sync(0xffffffffu, m, off));
    float e = __expf(x0 - m) + ((lane < 8) ? __expf(x1 - m) : 0.0f);
#pragma unroll
    for (int off = 16; off > 0; off >>= 1)
        e += __shfl_xor_sync(0xffffffffu, e, off);
    float ls = logf(e);
    float* o = out + (size_t)w * NCLS;
    o[lane] = x0 - m - ls;
    if (lane < 8) o[32 + lane] = x1 - m - ls;
}

// ---------------------------------------------------------------------------
extern "C" void kernel_launch(void* const* d_in, const int* in_sizes, int n_in,
                              void* d_out, int out_size)
{
    const float* x    = (const float*)d_in[0];
    const int*   esrc = (const int*)  d_in[1];
    const int*   edst = (const int*)  d_in[2];
    const int*   prow = (const int*)  d_in[3];
    const int*   pcol = (const int*)  d_in[4];
    const float* pval = (const float*)d_in[5];
    const float* w1   = (const float*)d_in[6];
    const float* b1   = (const float*)d_in[7];
    const float* w2   = (const float*)d_in[8];
    const float* b2   = (const float*)d_in[9];
    const float* wfc  = (const float*)d_in[10];
    const float* bfc  = (const float*)d_in[11];
    const int E   = in_sizes[1];
    const int nnz = in_sizes[3];

    __half *Y1h, *Y2h, *h1h, *h2h, *w1t, *w2t, *wfct;
    float *bfcp, *logits, *agg;
    int *ssrc, *rowStart, *deg, *cursor;
    cudaGetSymbolAddress((void**)&Y1h,      g_Y1h);
    cudaGetSymbolAddress((void**)&Y2h,      g_Y2h);
    cudaGetSymbolAddress((void**)&h1h,      g_h1h);
    cudaGetSymbolAddress((void**)&h2h,      g_h2h);
    cudaGetSymbolAddress((void**)&w1t,      g_w1t);
    cudaGetSymbolAddress((void**)&w2t,      g_w2t);
    cudaGetSymbolAddress((void**)&wfct,     g_wfct);
    cudaGetSymbolAddress((void**)&bfcp,     g_bfcp);
    cudaGetSymbolAddress((void**)&logits,   g_logits);
    cudaGetSymbolAddress((void**)&agg,      g_agg);
    cudaGetSymbolAddress((void**)&ssrc,     g_sortedSrc);
    cudaGetSymbolAddress((void**)&rowStart, g_rowStart);
    cudaGetSymbolAddress((void**)&deg,      g_deg);
    cudaGetSymbolAddress((void**)&cursor,   g_cursor);

    static cudaStream_t side = nullptr;
    static cudaEvent_t evFork = nullptr, evCSR = nullptr, evJoin = nullptr;
    static cudaEvent_t evA[NCHUNK] = {};
    if (!side) {
        cudaStreamCreateWithFlags(&side, cudaStreamNonBlocking);
        cudaEventCreateWithFlags(&evFork, cudaEventDisableTiming);
        cudaEventCreateWithFlags(&evCSR,  cudaEventDisableTiming);
        cudaEventCreateWithFlags(&evJoin, cudaEventDisableTiming);
        for (int c = 0; c < NCHUNK; c++)
            cudaEventCreateWithFlags(&evA[c], cudaEventDisableTiming);
    }

    // --- fork: CSR build + converts for later stages on side stream ---
    cudaEventRecord(evFork, 0);
    cudaStreamWaitEvent(side, evFork, 0);
    zero2_i32<<<(N_NODES + 255) / 256, 256, 0, side>>>(deg, cursor, N_NODES);
    hist_kernel<<<(E + 255) / 256, 256, 0, side>>>(edst, deg, E);
    scan_kernel<<<1, 1024, 0, side>>>(deg, rowStart);
    scatter_kernel<<<(E + 255) / 256, 256, 0, side>>>(esrc, edst, rowStart,
                                                      cursor, ssrc, E);
    cudaEventRecord(evCSR, side);
    zero_f32<<<(N_NODES * NCLS + 255) / 256, 256, 0, side>>>(agg,
                                                             N_NODES * NCLS);
    wconv_kernel<<<FDIM, FDIM, 0, side>>>(w2, w2t);
    wfc_conv_kernel<<<NPAD, FDIM, 0, side>>>(wfc, wfct);
    bfc_pad_kernel<<<1, NPAD, 0, side>>>(bfc, bfcp);

    // --- main: W1 convert + conv1 GEMM (reads fp32 x directly) ---
    wconv_kernel<<<FDIM, FDIM>>>(w1, w1t);
    dim3 g1_grid(FDIM / 128, (N_NODES + 127) / 128);
    gemm_mma<true><<<g1_grid, 256>>>(x, w1t, b1, Y1h, 0);

    // --- A1 (main, chunked) pipelined with G2 (side, chunked) ---
    cudaStreamWaitEvent(0, evCSR, 0);
    for (int c = 0; c < NCHUNK; c++) {
        int n0 = c * CHUNK_ROWS;
        int n1 = min(N_NODES, n0 + CHUNK_ROWS);
        int nb = (n1 - n0 + 7) / 8;
        aggregate_csr_h<<<nb, 256>>>(Y1h, h1h, rowStart, ssrc, n0, n1);
        cudaEventRecord(evA[c], 0);
        cudaStreamWaitEvent(side, evA[c], 0);
        dim3 g2_grid(FDIM / 128, (n1 - n0 + 127) / 128);
        gemm_mma<false><<<g2_grid, 256, 0, side>>>(h1h, w2t, b2, Y2h, n0);
    }
    cudaEventRecord(evJoin, side);
    cudaStreamWaitEvent(0, evJoin, 0);

    // --- A2 + head (main) ---
    aggregate_csr_h<<<(N_NODES + 7) / 8, 256>>>(Y2h, h2h, rowStart, ssrc,
                                                0, N_NODES);
    fc_mma<<<dim3(1, (N_NODES + 127) / 128), 256>>>(h2h, wfct, bfcp, logits);
    pvt_kernel<<<(int)(((long long)nnz * 32 + 255) / 256), 256>>>(
        logits, agg, prow, pcol, pval, nnz);
    logsoftmax_kernel<<<(int)(((long long)N_NODES * 32 + 255) / 256), 256>>>(
        agg, (float*)d_out);
}